// round 7
// baseline (speedup 1.0000x reference)
#include <cuda_runtime.h>
#include <cuda_fp16.h>
#include <math.h>
#include <stdint.h>

#define Bn 8
#define Ln 2048
#define Dn 1024
#define M_ALL (Bn * Ln)   // 16384

// ---------------------------------------------------------------------------
// Device scratch (allocation-free rule -> __device__ globals)
// ---------------------------------------------------------------------------
__device__ float g_ctx_scratch[(size_t)M_ALL * Dn];
__device__ float g_attn_scratch[(size_t)Bn * Ln * Ln];
__device__ float g_vmean[(size_t)Bn * Dn];
__device__ float g_xmean[(size_t)Bn * Dn];
__device__ int   g_lens[Bn];

// fp16 hi/lo planes
__device__ __half g_Xh[(size_t)M_ALL * Dn];
__device__ __half g_Xl[(size_t)M_ALL * Dn];
__device__ __half g_Oh[(size_t)M_ALL * Dn];
__device__ __half g_Ol[(size_t)M_ALL * Dn];
__device__ __half g_Wvh[(size_t)Dn * Dn];
__device__ __half g_Wvl[(size_t)Dn * Dn];
__device__ __half g_WqTh[(size_t)Dn * Dn];
__device__ __half g_WqTl[(size_t)Dn * Dn];
__device__ __half g_WkTh[(size_t)Dn * Dn];
__device__ __half g_WkTl[(size_t)Dn * Dn];
__device__ __half g_GTh[(size_t)Dn * Dn];
__device__ __half g_GTl[(size_t)Dn * Dn];
__device__ __half g_QGh[(size_t)M_ALL * Dn];
__device__ __half g_QGl[(size_t)M_ALL * Dn];
__device__ __half g_XTh[(size_t)Bn * Dn * Ln];
__device__ __half g_XTl[(size_t)Bn * Dn * Ln];
__device__ __half g_Ph[(size_t)M_ALL * Ln];
__device__ __half g_Pl[(size_t)M_ALL * Ln];
__device__ __half g_PXh[(size_t)M_ALL * Dn];
__device__ __half g_PXl[(size_t)M_ALL * Dn];

// ---------------------------------------------------------------------------
// lens dtype sniffing (int64 vs int32)
// ---------------------------------------------------------------------------
__global__ void prep_lens_kernel(const void* lensraw) {
    if (threadIdx.x == 0 && blockIdx.x == 0) {
        const int* a32 = (const int*)lensraw;
        bool is64 = true;
        #pragma unroll
        for (int i = 0; i < 4; i++) {
            int lo = a32[2 * i], hi = a32[2 * i + 1];
            if (hi != 0 || lo < 1 || lo > Ln) { is64 = false; break; }
        }
        if (is64) {
            const long long* a64 = (const long long*)lensraw;
            for (int i = 0; i < Bn; i++) g_lens[i] = (int)a64[i];
        } else {
            for (int i = 0; i < Bn; i++) g_lens[i] = a32[i];
        }
    }
}

// ---------------------------------------------------------------------------
// fp32 -> (hi, lo) fp16 planes, flat
// ---------------------------------------------------------------------------
__global__ __launch_bounds__(256)
void expand2_kernel(const float* __restrict__ src, __half* __restrict__ dh,
                    __half* __restrict__ dl, long long total4) {
    long long i = (long long)blockIdx.x * blockDim.x + threadIdx.x;
    if (i >= total4) return;
    float4 v = *(const float4*)(src + i * 4);
    float vv[4] = {v.x, v.y, v.z, v.w};
    unsigned short hb[4], lb[4];
    #pragma unroll
    for (int j = 0; j < 4; j++) {
        __half hbf = __float2half_rn(vv[j]);
        float hf = __half2float(hbf);
        __half lbf = __float2half_rn(vv[j] - hf);
        hb[j] = __half_as_ushort(hbf);
        lb[j] = __half_as_ushort(lbf);
    }
    *(ushort4*)(dh + i * 4) = make_ushort4(hb[0], hb[1], hb[2], hb[3]);
    *(ushort4*)(dl + i * 4) = make_ushort4(lb[0], lb[1], lb[2], lb[3]);
}

// ---------------------------------------------------------------------------
// Transpose fp32 [R,C] -> fp16 hi/lo planes [C,R]; batched via blockIdx.z.
// ---------------------------------------------------------------------------
__global__ __launch_bounds__(256)
void trans_kernel(const float* __restrict__ src, __half* __restrict__ oh,
                  __half* __restrict__ ol, int R, int C) {
    __shared__ float tile[32][33];
    size_t bo = (size_t)blockIdx.z * R * C;
    src += bo; oh += bo; ol += bo;
    int c0 = blockIdx.x * 32;
    int r0 = blockIdx.y * 32;
    int tx = threadIdx.x & 31;
    int ty = threadIdx.x >> 5;

    #pragma unroll
    for (int j = 0; j < 4; j++)
        tile[ty + j * 8][tx] = src[(size_t)(r0 + ty + j * 8) * C + c0 + tx];
    __syncthreads();

    #pragma unroll
    for (int j = 0; j < 4; j++) {
        float v = tile[tx][ty + j * 8];
        __half h = __float2half_rn(v);
        __half l = __float2half_rn(v - __half2float(h));
        size_t o = (size_t)(c0 + ty + j * 8) * R + r0 + tx;
        oh[o] = h;
        ol[o] = l;
    }
}

// ---------------------------------------------------------------------------
// xmean[b][d] = (1/2048) * sum_t X[b*Ln+t][d]
// ---------------------------------------------------------------------------
__global__ __launch_bounds__(256)
void xmean_kernel(const float* __restrict__ xf, float* __restrict__ xm) {
    int b = blockIdx.y;
    int d = blockIdx.x * 256 + threadIdx.x;
    const float* p = xf + (size_t)b * Ln * Dn + d;
    float s0 = 0.f, s1 = 0.f, s2 = 0.f, s3 = 0.f;
    for (int t = 0; t < Ln; t += 4) {
        s0 += p[(size_t)(t + 0) * Dn];
        s1 += p[(size_t)(t + 1) * Dn];
        s2 += p[(size_t)(t + 2) * Dn];
        s3 += p[(size_t)(t + 3) * Dn];
    }
    xm[b * Dn + d] = (s0 + s1 + s2 + s3) * (1.0f / 2048.0f);
}

// ---------------------------------------------------------------------------
// vmean[b][e] = sum_d xmean[b][d] * Wv[e][d]
// ---------------------------------------------------------------------------
__global__ __launch_bounds__(256)
void vmeanw_kernel(const float* __restrict__ xm, const float* __restrict__ Wv,
                   float* __restrict__ vm) {
    int b = blockIdx.y;
    int e = blockIdx.x * 8 + (threadIdx.x >> 5);
    int lane = threadIdx.x & 31;
    const float* xr = xm + b * Dn;
    const float* wr = Wv + (size_t)e * Dn;
    float s = 0.f;
    for (int d = lane; d < Dn; d += 32) s += xr[d] * wr[d];
    #pragma unroll
    for (int o = 16; o > 0; o >>= 1) s += __shfl_down_sync(0xffffffffu, s, o);
    if (lane == 0) vm[b * Dn + e] = s;
}

// ---------------------------------------------------------------------------
// Fill masked ctx rows with vmean
// ---------------------------------------------------------------------------
__global__ __launch_bounds__(256)
void fill_masked_kernel(const float* __restrict__ vm, float* __restrict__ ctx) {
    int b = blockIdx.z;
    int q = blockIdx.y;
    if (q < g_lens[b]) return;
    int d = blockIdx.x * 256 + threadIdx.x;
    ctx[((size_t)b * Ln + q) * Dn + d] = vm[b * Dn + d];
}

// ---------------------------------------------------------------------------
// HMMA GEMM core (mma.sync m16n8k16 fp16, fp32 accum), NT.
// 3 K-segments over hi/lo planes: (Ah,Bh), (Ah,Bl), (Al,Bh).
// CTA tile 128(M) x 256(N), BK=64, 4-stage cp.async, 8 warps 2x4,
// warp tile 64x64 (32 FLOP per smem byte -> crossbar no longer binding).
// MODE 0: fp32 C. MODE 1: scale+mask fp32 C. MODE 2: write hi/lo fp16 planes.
// skipMode 1: skip tile if local row0 >= lens[z]
// skipMode 2: skip tile if (row0 & 2047) >= lens[row0 >> 11]
// ---------------------------------------------------------------------------
__device__ __forceinline__ uint32_t sw128(uint32_t x) { return x ^ ((x >> 3) & 0x70); }

#define A_BYTES 16384
#define STAGE_B 49152
#define NSTAGE  4
#define SMEM_REQ (1024 + NSTAGE * STAGE_B)

__device__ __forceinline__ void cp16(uint32_t saddr, const void* gaddr) {
    asm volatile("cp.async.cg.shared.global [%0], [%1], 16;" :: "r"(saddr), "l"(gaddr));
}
__device__ __forceinline__ void cp_commit() {
    asm volatile("cp.async.commit_group;" ::: "memory");
}
template <int N> __device__ __forceinline__ void cp_wait() {
    asm volatile("cp.async.wait_group %0;" :: "n"(N) : "memory");
}
__device__ __forceinline__ void ldm4(uint32_t addr, uint32_t& r0, uint32_t& r1,
                                     uint32_t& r2, uint32_t& r3) {
    asm volatile("ldmatrix.sync.aligned.m8n8.x4.shared.b16 {%0,%1,%2,%3}, [%4];"
                 : "=r"(r0), "=r"(r1), "=r"(r2), "=r"(r3) : "r"(addr));
}
__device__ __forceinline__ void mma16816(float* c, uint32_t a0, uint32_t a1,
                                         uint32_t a2, uint32_t a3,
                                         uint32_t b0, uint32_t b1) {
    asm volatile(
        "mma.sync.aligned.m16n8k16.row.col.f32.f16.f16.f32 "
        "{%0,%1,%2,%3},{%4,%5,%6,%7},{%8,%9},{%0,%1,%2,%3};"
        : "+f"(c[0]), "+f"(c[1]), "+f"(c[2]), "+f"(c[3])
        : "r"(a0), "r"(a1), "r"(a2), "r"(a3), "r"(b0), "r"(b1));
}
__device__ __forceinline__ uint32_t pack_h2(__half a, __half b) {
    return (uint32_t)__half_as_ushort(a) | ((uint32_t)__half_as_ushort(b) << 16);
}

template <int MODE>
__global__ __launch_bounds__(256, 1)
void hmma_gemm(const __half* __restrict__ Ah, const __half* __restrict__ Al,
               const __half* __restrict__ Bh, const __half* __restrict__ Bl,
               float* __restrict__ C,
               __half* __restrict__ Poh, __half* __restrict__ Pol,
               int K, int ldc,
               long long sA, long long sB, long long sC, float scale, int skipMode) {
    const int z    = blockIdx.z;
    const int row0 = blockIdx.y * 128;
    const int n0   = blockIdx.x * 256;

    if (skipMode == 1) {
        if (row0 >= g_lens[z]) return;
    } else if (skipMode == 2) {
        if ((row0 & (Ln - 1)) >= g_lens[row0 >> 11]) return;
    }

    extern __shared__ char dsm[];
    uint32_t sraw = (uint32_t)__cvta_generic_to_shared(dsm);
    uint32_t sb   = (sraw + 1023) & ~1023u;

    const int tid  = threadIdx.x;
    const int lane = tid & 31;
    const int wid  = tid >> 5;
    const int wr   = wid >> 2;     // 0..1 : M 64-row half
    const int wc   = wid & 3;      // 0..3 : N 64-col quarter

    // loader assignment
    const int ra = tid >> 1;               // A row 0..127
    const int ha = (tid & 1) * 64;         // A 64B half
    const int rb = tid;                    // B row 0..255 (full 128B row)

    const char* aRowH = (const char*)(Ah + (size_t)z * sA + (size_t)(row0 + ra) * K) + ha;
    const char* aRowL = (const char*)(Al + (size_t)z * sA + (size_t)(row0 + ra) * K) + ha;
    const char* bRowH = (const char*)(Bh + (size_t)z * sB + (size_t)(n0 + rb) * K);
    const char* bRowL = (const char*)(Bl + (size_t)z * sB + (size_t)(n0 + rb) * K);

    uint32_t swoA[4], swoB[8];
    #pragma unroll
    for (int i = 0; i < 4; i++) swoA[i] = sw128((uint32_t)ra * 128u + ha + i * 16);
    #pragma unroll
    for (int i = 0; i < 8; i++) swoB[i] = sw128((uint32_t)rb * 128u + i * 16);

    float acc[4][8][4];
    #pragma unroll
    for (int a = 0; a < 4; a++)
        #pragma unroll
        for (int b = 0; b < 8; b++)
            #pragma unroll
            for (int cc = 0; cc < 4; cc++) acc[a][b][cc] = 0.0f;

    const int nch = K / 64;
    const int T   = 3 * nch;

    const char* aPtr = aRowH;
    const char* bPtr = bRowH;
    int cIss = 0, segIss = 0, bufIss = 0;

    auto issue_one = [&]() {
        uint32_t sa = sb + bufIss * STAGE_B;
        #pragma unroll
        for (int i = 0; i < 4; i++) cp16(sa + swoA[i], aPtr + i * 16);
        uint32_t sbB = sa + A_BYTES;
        #pragma unroll
        for (int i = 0; i < 8; i++) cp16(sbB + swoB[i], bPtr + i * 16);
        cp_commit();
        aPtr += 128; bPtr += 128;
        bufIss = (bufIss == NSTAGE - 1) ? 0 : bufIss + 1;
        if (++cIss == nch) {
            cIss = 0; segIss++;
            if (segIss == 1)      { aPtr = aRowH; bPtr = bRowL; }
            else if (segIss == 2) { aPtr = aRowL; bPtr = bRowH; }
        }
    };

    issue_one();
    issue_one();
    issue_one();

    int bufC = 0;
    for (int t = 0; t < T; t++) {
        if (t + 3 < T)      { issue_one(); cp_wait<3>(); }
        else if (t + 2 < T) { cp_wait<2>(); }
        else if (t + 1 < T) { cp_wait<1>(); }
        else                { cp_wait<0>(); }
        __syncthreads();

        const uint32_t aBase = sb + bufC * STAGE_B;
        const uint32_t bBase = aBase + A_BYTES;

        #pragma unroll
        for (int kk = 0; kk < 4; kk++) {
            uint32_t af[4][4];
            #pragma unroll
            for (int mi = 0; mi < 4; mi++) {
                uint32_t row  = wr * 64 + mi * 16 + (lane & 15);
                uint32_t colb = kk * 32 + ((lane >> 4) << 4);
                ldm4(aBase + sw128(row * 128u + colb), af[mi][0], af[mi][1], af[mi][2], af[mi][3]);
            }
            uint32_t bf[4][4];
            #pragma unroll
            for (int ni = 0; ni < 4; ni++) {
                uint32_t q    = lane >> 3;
                uint32_t row  = wc * 64 + ni * 16 + ((q >> 1) << 3) + (lane & 7);
                uint32_t colb = kk * 32 + ((q & 1) << 4);
                ldm4(bBase + sw128(row * 128u + colb), bf[ni][0], bf[ni][1], bf[ni][2], bf[ni][3]);
            }
            #pragma unroll
            for (int mi = 0; mi < 4; mi++)
                #pragma unroll
                for (int n8 = 0; n8 < 8; n8++) {
                    uint32_t b0 = bf[n8 >> 1][(n8 & 1) * 2 + 0];
                    uint32_t b1 = bf[n8 >> 1][(n8 & 1) * 2 + 1];
                    mma16816(acc[mi][n8], af[mi][0], af[mi][1], af[mi][2], af[mi][3], b0, b1);
                }
        }
        __syncthreads();
        bufC = (bufC == NSTAGE - 1) ? 0 : bufC + 1;
    }

    // ---- epilogue
    const int g  = lane >> 2;
    const int tg = lane & 3;
    const int len = (MODE == 1) ? g_lens[z] : 0;

    #pragma unroll
    for (int mi = 0; mi < 4; mi++) {
        const int rA = row0 + wr * 64 + mi * 16 + g;
        const int rB = rA + 8;
        #pragma unroll
        for (int n8 = 0; n8 < 8; n8++) {
            const int col = n0 + wc * 64 + n8 * 8 + tg * 2;
            float v0 = acc[mi][n8][0], v1 = acc[mi][n8][1];
            float v2 = acc[mi][n8][2], v3 = acc[mi][n8][3];
            if (MODE == 0) {
                float* Cz = C + (size_t)z * sC;
                *(float2*)(Cz + (size_t)rA * ldc + col) = make_float2(v0, v1);
                *(float2*)(Cz + (size_t)rB * ldc + col) = make_float2(v2, v3);
            } else if (MODE == 1) {
                float* Cz = C + (size_t)z * sC;
                bool okA = rA < len, okB = rB < len;
                *(float2*)(Cz + (size_t)rA * ldc + col) =
                    make_float2(okA ? v0 * scale : -1e9f, okA ? v1 * scale : -1e9f);
                *(float2*)(Cz + (size_t)rB * ldc + col) =
                    make_float2(okB ? v2 * scale : -1e9f, okB ? v3 * scale : -1e9f);
            } else {
                __half* PohZ = Poh + (size_t)z * sC;
                __half* PolZ = Pol + (size_t)z * sC;
                __half h0 = __float2half_rn(v0), h1 = __float2half_rn(v1);
                __half h2 = __float2half_rn(v2), h3 = __float2half_rn(v3);
                __half l0 = __float2half_rn(v0 - __half2float(h0));
                __half l1 = __float2half_rn(v1 - __half2float(h1));
                __half l2 = __float2half_rn(v2 - __half2float(h2));
                __half l3 = __float2half_rn(v3 - __half2float(h3));
                *(uint32_t*)(PohZ + (size_t)rA * ldc + col) = pack_h2(h0, h1);
                *(uint32_t*)(PohZ + (size_t)rB * ldc + col) = pack_h2(h2, h3);
                *(uint32_t*)(PolZ + (size_t)rA * ldc + col) = pack_h2(l0, l1);
                *(uint32_t*)(PolZ + (size_t)rB * ldc + col) = pack_h2(l2, l3);
            }
        }
    }
}

// ---------------------------------------------------------------------------
// Row softmax over Ln=2048, in place + hi/lo fp16 plane outputs.
// Masked rows (q >= len): exact uniform 1/2048, no reads.
// ---------------------------------------------------------------------------
__global__ __launch_bounds__(256)
void softmax_kernel(float* __restrict__ attn, __half* __restrict__ Ph,
                    __half* __restrict__ Pl) {
    const size_t row = blockIdx.x;
    const int b  = (int)(row >> 11);
    const int ql = (int)(row & (Ln - 1));
    float* p = attn + row * Ln;
    const int t = threadIdx.x;

    if (ql >= g_lens[b]) {
        const float u = 1.0f / 2048.0f;
        const unsigned short uh = __half_as_ushort(__float2half_rn(u));
        float4 uv = make_float4(u, u, u, u);
        ((float4*)p)[t * 2]     = uv;
        ((float4*)p)[t * 2 + 1] = uv;
        ushort4 us = make_ushort4(uh, uh, uh, uh);
        ushort4 zs = make_ushort4(0, 0, 0, 0);
        __half* ph = Ph + row * Ln + t * 8;
        __half* pl = Pl + row * Ln + t * 8;
        *(ushort4*)(ph) = us; *(ushort4*)(ph + 4) = us;
        *(ushort4*)(pl) = zs; *(ushort4*)(pl + 4) = zs;
        return;
    }

    float4 va = ((const float4*)p)[t * 2];
    float4 vb = ((const float4*)p)[t * 2 + 1];
    float v[8] = {va.x, va.y, va.z, va.w, vb.x, vb.y, vb.z, vb.w};

    float m = v[0];
    #pragma unroll
    for (int i = 1; i < 8; i++) m = fmaxf(m, v[i]);

    __shared__ float red[256];
    red[t] = m;
    __syncthreads();
    #pragma unroll
    for (int s = 128; s > 0; s >>= 1) {
        if (t < s) red[t] = fmaxf(red[t], red[t + s]);
        __syncthreads();
    }
    m = red[0];
    __syncthreads();

    float sum = 0.0f;
    #pragma unroll
    for (int i = 0; i < 8; i++) {
        v[i] = expf(v[i] - m);
        sum += v[i];
    }
    red[t] = sum;
    __syncthreads();
    #pragma unroll
    for (int s = 128; s > 0; s >>= 1) {
        if (t < s) red[t] += red[t + s];
        __syncthreads();
    }
    const float inv = 1.0f / red[0];

    unsigned short hb[8], lb[8];
    #pragma unroll
    for (int i = 0; i < 8; i++) {
        v[i] *= inv;
        __half hbf = __float2half_rn(v[i]);
        float hf = __half2float(hbf);
        __half lbf = __float2half_rn(v[i] - hf);
        hb[i] = __half_as_ushort(hbf);
        lb[i] = __half_as_ushort(lbf);
    }
    ((float4*)p)[t * 2]     = make_float4(v[0], v[1], v[2], v[3]);
    ((float4*)p)[t * 2 + 1] = make_float4(v[4], v[5], v[6], v[7]);
    __half* ph = Ph + row * Ln + t * 8;
    __half* pl = Pl + row * Ln + t * 8;
    *(ushort4*)(ph)     = make_ushort4(hb[0], hb[1], hb[2], hb[3]);
    *(ushort4*)(ph + 4) = make_ushort4(hb[4], hb[5], hb[6], hb[7]);
    *(ushort4*)(pl)     = make_ushort4(lb[0], lb[1], lb[2], lb[3]);
    *(ushort4*)(pl + 4) = make_ushort4(lb[4], lb[5], lb[6], lb[7]);
}

// ---------------------------------------------------------------------------
// kernel_launch
// ---------------------------------------------------------------------------
extern "C" void kernel_launch(void* const* d_in, const int* in_sizes, int n_in,
                              void* d_out, int out_size) {
    const float* X  = (const float*)d_in[0];
    const void*  lens_raw = d_in[1];
    const float* O  = (const float*)d_in[2];
    const float* Wk = (const float*)d_in[3];
    const float* Wv = (const float*)d_in[4];
    const float* Wq = (const float*)d_in[5];

    const long long CTX = (long long)Bn * Ln * Dn;
    const long long ATT = (long long)Bn * Ln * Ln;

    float *ctx_s, *attn_s, *vm, *xm;
    __half *Xh, *Xl, *Oh, *Ol, *Wvh, *Wvl, *WqTh, *WqTl, *WkTh, *WkTl;
    __half *GTh, *GTl, *QGh, *QGl, *XTh, *XTl, *Ph, *Pl, *PXh, *PXl;
    cudaGetSymbolAddress((void**)&ctx_s, g_ctx_scratch);
    cudaGetSymbolAddress((void**)&attn_s, g_attn_scratch);
    cudaGetSymbolAddress((void**)&vm, g_vmean);
    cudaGetSymbolAddress((void**)&xm, g_xmean);
    cudaGetSymbolAddress((void**)&Xh, g_Xh);   cudaGetSymbolAddress((void**)&Xl, g_Xl);
    cudaGetSymbolAddress((void**)&Oh, g_Oh);   cudaGetSymbolAddress((void**)&Ol, g_Ol);
    cudaGetSymbolAddress((void**)&Wvh, g_Wvh); cudaGetSymbolAddress((void**)&Wvl, g_Wvl);
    cudaGetSymbolAddress((void**)&WqTh, g_WqTh); cudaGetSymbolAddress((void**)&WqTl, g_WqTl);
    cudaGetSymbolAddress((void**)&WkTh, g_WkTh); cudaGetSymbolAddress((void**)&WkTl, g_WkTl);
    cudaGetSymbolAddress((void**)&GTh, g_GTh); cudaGetSymbolAddress((void**)&GTl, g_GTl);
    cudaGetSymbolAddress((void**)&QGh, g_QGh); cudaGetSymbolAddress((void**)&QGl, g_QGl);
    cudaGetSymbolAddress((void**)&XTh, g_XTh); cudaGetSymbolAddress((void**)&XTl, g_XTl);
    cudaGetSymbolAddress((void**)&Ph, g_Ph);   cudaGetSymbolAddress((void**)&Pl, g_Pl);
    cudaGetSymbolAddress((void**)&PXh, g_PXh); cudaGetSymbolAddress((void**)&PXl, g_PXl);

    float* ctx;
    float* attn;
    if ((long long)out_size >= CTX + ATT) {
        ctx  = (float*)d_out;
        attn = (float*)d_out + CTX;
    } else if ((long long)out_size == ATT) {
        attn = (float*)d_out;
        ctx  = ctx_s;
    } else {
        ctx  = (float*)d_out;
        attn = attn_s;
    }

    cudaFuncSetAttribute(hmma_gemm<0>, cudaFuncAttributeMaxDynamicSharedMemorySize, SMEM_REQ);
    cudaFuncSetAttribute(hmma_gemm<1>, cudaFuncAttributeMaxDynamicSharedMemorySize, SMEM_REQ);
    cudaFuncSetAttribute(hmma_gemm<2>, cudaFuncAttributeMaxDynamicSharedMemorySize, SMEM_REQ);

    prep_lens_kernel<<<1, 32>>>(lens_raw);

    // Expansions + transposes of raw inputs
    {
        long long t4 = (long long)M_ALL * Dn / 4;
        int blocks = (int)((t4 + 255) / 256);
        expand2_kernel<<<blocks, 256>>>(X, Xh, Xl, t4);
        expand2_kernel<<<blocks, 256>>>(O, Oh, Ol, t4);
        long long w4 = (long long)Dn * Dn / 4;
        int wb = (int)((w4 + 255) / 256);
        expand2_kernel<<<wb, 256>>>(Wv, Wvh, Wvl, w4);
        trans_kernel<<<dim3(Dn / 32, Dn / 32, 1), 256>>>(Wq, WqTh, WqTl, Dn, Dn);
        trans_kernel<<<dim3(Dn / 32, Dn / 32, 1), 256>>>(Wk, WkTh, WkTl, Dn, Dn);
        trans_kernel<<<dim3(Dn / 32, Ln / 32, Bn), 256>>>(X, XTh, XTl, Ln, Dn);
    }

    // vmean = (mean_t X) @ Wv^T  (exact fp32 path for masked ctx rows)
    xmean_kernel<<<dim3(Dn / 256, Bn), 256>>>(X, xm);
    vmeanw_kernel<<<dim3(Dn / 8, Bn), 256>>>(xm, Wv, vm);

    // GT = Wk^T @ Wq
    hmma_gemm<2><<<dim3(Dn / 256, Dn / 128, 1), 256, SMEM_REQ>>>(
        WkTh, WkTl, WqTh, WqTl, nullptr, GTh, GTl, Dn, Dn, 0, 0, 0, 1.0f, 0);

    // QG = O @ G; masked row tiles skipped
    hmma_gemm<2><<<dim3(Dn / 256, M_ALL / 128, 1), 256, SMEM_REQ>>>(
        Oh, Ol, GTh, GTl, nullptr, QGh, QGl, Dn, Dn, 0, 0, 0, 1.0f, 2);

    // scores = QG @ X^T / 32, per batch, query-mask epilogue, masked tiles skipped
    hmma_gemm<1><<<dim3(Ln / 256, Ln / 128, Bn), 256, SMEM_REQ>>>(
        QGh, QGl, Xh, Xl, attn, nullptr, nullptr, Dn, Ln,
        (long long)Ln * Dn, (long long)Ln * Dn, (long long)Ln * Ln, 0.03125f, 1);

    // Softmax in place + P hi/lo planes (uniform fill for masked rows)
    softmax_kernel<<<Bn * Ln, 256>>>(attn, Ph, Pl);

    // PX = P @ X per batch; masked tiles skipped
    hmma_gemm<2><<<dim3(Dn / 256, Ln / 128, Bn), 256, SMEM_REQ>>>(
        Ph, Pl, XTh, XTl, nullptr, PXh, PXl, Ln, Dn,
        (long long)Ln * Ln, (long long)Dn * Ln, (long long)Ln * Dn, 1.0f, 1);

    // ctx = PX @ Wv^T; masked tiles skipped
    hmma_gemm<0><<<dim3(Dn / 256, M_ALL / 128, 1), 256, SMEM_REQ>>>(
        PXh, PXl, Wvh, Wvl, ctx, nullptr, nullptr, Dn, Dn, 0, 0, 0, 1.0f, 2);

    // Masked ctx rows = per-batch V mean
    fill_masked_kernel<<<dim3(Dn / 256, Ln, Bn), 256>>>(vm, ctx);
}